// round 4
// baseline (speedup 1.0000x reference)
#include <cuda_runtime.h>
#include <math_constants.h>

// ---------------------------------------------------------------------------
// CNNTest: graph conv (1->32) -> graph conv (32->64) -> FC(64->512) -> softmax
// V = 100000, N = 32 neighbors.
//
// R3 change (resubmitted R4 after infra timeout): k_out inner loop uses packed
// fp32 FFMA2 (fma.rn.f32x2, sm_103a) for 2x fp32 FMA throughput; B loads
// widened to 128-bit v2.u64; columns per lane made contiguous (ln*16..+15).
// Everything else identical to R2 baseline (424us).
// ---------------------------------------------------------------------------

#define V_MAX 100352
#define NNB   32

__device__ float g_h [V_MAX];
__device__ float g_f1[V_MAX * 32];
__device__ float g_h2[V_MAX * 32];
__device__ float g_Wc[96 * 512];
__device__ float g_bc[512];

// --------------------------- packed f32x2 helpers ---------------------------
__device__ __forceinline__ unsigned long long pack2(float x, float y) {
    unsigned long long r;
    asm("mov.b64 %0, {%1, %2};" : "=l"(r) : "f"(x), "f"(y));
    return r;
}
__device__ __forceinline__ void unpack2(unsigned long long p, float& x, float& y) {
    asm("mov.b64 {%0, %1}, %2;" : "=f"(x), "=f"(y) : "l"(p));
}
__device__ __forceinline__ unsigned long long ffma2(unsigned long long a,
                                                    unsigned long long b,
                                                    unsigned long long c) {
    unsigned long long d;
    asm("fma.rn.f32x2 %0, %1, %2, %3;" : "=l"(d) : "l"(a), "l"(b), "l"(c));
    return d;
}
__device__ __forceinline__ unsigned long long add2(unsigned long long a,
                                                   unsigned long long b) {
    unsigned long long d;
    asm("add.rn.f32x2 %0, %1, %2;" : "=l"(d) : "l"(a), "l"(b));
    return d;
}

// --------------------------- K1: first graph conv (to scalar h) ------------
__global__ void k_h(const float* __restrict__ vp, const int* __restrict__ nb1,
                    const float* __restrict__ wv1, const float* __restrict__ bv1,
                    int V) {
    int t = blockIdx.x * blockDim.x + threadIdx.x;
    int v = t >> 5;
    int j = t & 31;
    if (v >= V) return;
    float w0 = wv1[0], w1c = wv1[1], w2c = wv1[2], b = bv1[0];

    int   idx = nb1[v * NNB + j];
    float g   = vp[idx];
    float gm  = __shfl_up_sync(0xffffffffu, g, 1);
    float gp  = __shfl_down_sync(0xffffffffu, g, 1);
    if (j == 0)  gm = 0.f;
    if (j == 31) gp = 0.f;
    float c = fmaf(w0, gm, fmaf(w1c, g, fmaf(w2c, gp, b)));
    float r = fmaxf(c, 0.f);
#pragma unroll
    for (int s = 16; s > 0; s >>= 1)
        r += __shfl_xor_sync(0xffffffffu, r, s);
    if (j == 0) g_h[v] = r * (1.f / 32.f);
}

// --------------------------- K2: vertex conv 1 -> 32 channels --------------
__global__ void k_f1(const float* __restrict__ w1, const float* __restrict__ b1,
                     int V) {
    int t = blockIdx.x * blockDim.x + threadIdx.x;
    if (t >= V * 32) return;
    int v = t >> 5;
    int o = t & 31;
    float hm = (v > 0)     ? g_h[v - 1] : 0.f;
    float h0 = g_h[v];
    float hp = (v < V - 1) ? g_h[v + 1] : 0.f;
    g_f1[t] = fmaf(hm, w1[o * 3 + 0],
              fmaf(h0, w1[o * 3 + 1],
              fmaf(hp, w1[o * 3 + 2], b1[o])));
}

// --------------------------- K3: second graph conv (neighbor axis) ---------
__global__ void k_h2(const int* __restrict__ nb2,
                     const float* __restrict__ wv2, const float* __restrict__ bv2,
                     int V) {
    int t = blockIdx.x * blockDim.x + threadIdx.x;
    int v = t >> 5;
    int c = t & 31;
    if (v >= V) return;
    float w0 = wv2[0], w1c = wv2[1], w2c = wv2[2], b = bv2[0];

    int myidx = nb2[v * NNB + c];
    float g[32];
#pragma unroll
    for (int j = 0; j < 32; j++) {
        int ij = __shfl_sync(0xffffffffu, myidx, j);
        g[j] = g_f1[ij * 32 + c];
    }
    float acc = 0.f;
#pragma unroll
    for (int j = 0; j < 32; j++) {
        float gm = (j > 0)  ? g[j - 1] : 0.f;
        float gp = (j < 31) ? g[j + 1] : 0.f;
        acc += fmaxf(fmaf(w0, gm, fmaf(w1c, g[j], fmaf(w2c, gp, b))), 0.f);
    }
    g_h2[v * 32 + c] = acc * (1.f / 32.f);
}

// --------------------------- Kpre: fold w2 into wfc ------------------------
__global__ void k_pre(const float* __restrict__ w2, const float* __restrict__ wfc,
                      const float* __restrict__ b2, const float* __restrict__ bfc) {
    int p = threadIdx.x;       // 0..511
    int blk = blockIdx.x;      // 0..96
    if (blk < 96) {
        int k3 = blk >> 5;
        int c  = blk & 31;
        float s = 0.f;
#pragma unroll
        for (int o = 0; o < 64; o++)
            s = fmaf(w2[o * 96 + c * 3 + k3], wfc[p * 64 + o], s);
        g_Wc[blk * 512 + p] = s;
    } else {
        float s = bfc[p];
#pragma unroll
        for (int o = 0; o < 64; o++)
            s = fmaf(b2[o], wfc[p * 64 + o], s);
        g_bc[p] = s;
    }
}

// --------------------------- K4: fused GEMM + bias + softmax (FFMA2) -------
// Block: 256 threads, 32 vertices. Warp w: rows w*4..w*4+3.
// Lane c: 16 CONTIGUOUS cols [c*16, c*16+16) held as 8 f32x2 pairs.
__global__ void __launch_bounds__(256, 2)
k_out(float* __restrict__ out, int V) {
    __shared__ float As[96 * 36];
    int tid = threadIdx.x;
    int wp  = tid >> 5;
    int ln  = tid & 31;
    int v0  = blockIdx.x * 32;

    // Build A panel: As[K][v] = h2[v0+v-1+k3][c], K = k3*32 + c
    for (int i = tid; i < 96 * 32; i += 256) {
        int K  = i % 96;
        int v  = i / 96;
        int k3 = K >> 5;
        int ch = K & 31;
        int row = v0 + v - 1 + k3;
        float val = (row >= 0 && row < V) ? g_h2[row * 32 + ch] : 0.f;
        As[K * 36 + v] = val;
    }
    __syncthreads();

    unsigned long long acc[4][8];
#pragma unroll
    for (int i = 0; i < 4; i++)
#pragma unroll
        for (int j = 0; j < 8; j++) acc[i][j] = 0ULL;   // (0.f, 0.f)

    const float* __restrict__ br = g_Wc + ln * 16;
#pragma unroll 4
    for (int k = 0; k < 96; k++) {
        float4 a = *(const float4*)&As[k * 36 + wp * 4];
        unsigned long long a0 = pack2(a.x, a.x);
        unsigned long long a1 = pack2(a.y, a.y);
        unsigned long long a2 = pack2(a.z, a.z);
        unsigned long long a3 = pack2(a.w, a.w);
        unsigned long long b[8];
#pragma unroll
        for (int q = 0; q < 4; q++)
            asm("ld.global.nc.v2.u64 {%0, %1}, [%2];"
                : "=l"(b[2 * q]), "=l"(b[2 * q + 1])
                : "l"(br + k * 512 + q * 4));
#pragma unroll
        for (int j = 0; j < 8; j++) {
            acc[0][j] = ffma2(a0, b[j], acc[0][j]);
            acc[1][j] = ffma2(a1, b[j], acc[1][j]);
            acc[2][j] = ffma2(a2, b[j], acc[2][j]);
            acc[3][j] = ffma2(a3, b[j], acc[3][j]);
        }
    }

    // bias (packed)
    unsigned long long bb[8];
#pragma unroll
    for (int q = 0; q < 4; q++)
        asm("ld.global.nc.v2.u64 {%0, %1}, [%2];"
            : "=l"(bb[2 * q]), "=l"(bb[2 * q + 1])
            : "l"(g_bc + ln * 16 + q * 4));

    // per-row softmax: row spans exactly one warp (16 contiguous cols/lane)
#pragma unroll
    for (int i = 0; i < 4; i++) {
        int v = v0 + wp * 4 + i;
        float vals[16];
        float m = -CUDART_INF_F;
#pragma unroll
        for (int j = 0; j < 8; j++) {
            unsigned long long s = add2(acc[i][j], bb[j]);
            unpack2(s, vals[2 * j], vals[2 * j + 1]);
            m = fmaxf(m, fmaxf(vals[2 * j], vals[2 * j + 1]));
        }
#pragma unroll
        for (int s = 16; s > 0; s >>= 1)
            m = fmaxf(m, __shfl_xor_sync(0xffffffffu, m, s));
        float sum = 0.f;
#pragma unroll
        for (int j = 0; j < 16; j++) {
            vals[j] = __expf(vals[j] - m);
            sum += vals[j];
        }
#pragma unroll
        for (int s = 16; s > 0; s >>= 1)
            sum += __shfl_xor_sync(0xffffffffu, sum, s);
        float inv = __fdividef(1.f, sum);
        if (v < V) {
            float* orow = out + (size_t)v * 512 + ln * 16;
#pragma unroll
            for (int q = 0; q < 4; q++) {
                float4 o;
                o.x = vals[4 * q + 0] * inv;
                o.y = vals[4 * q + 1] * inv;
                o.z = vals[4 * q + 2] * inv;
                o.w = vals[4 * q + 3] * inv;
                *(float4*)(orow + q * 4) = o;
            }
        }
    }
}

// ---------------------------------------------------------------------------
extern "C" void kernel_launch(void* const* d_in, const int* in_sizes, int n_in,
                              void* d_out, int out_size) {
    const float* vp  = (const float*)d_in[0];
    const int*   nb1 = (const int*)  d_in[1];
    const int*   nb2 = (const int*)  d_in[2];
    const float* wv1 = (const float*)d_in[3];
    const float* bv1 = (const float*)d_in[4];
    const float* w1  = (const float*)d_in[5];
    const float* b1  = (const float*)d_in[6];
    const float* wv2 = (const float*)d_in[7];
    const float* bv2 = (const float*)d_in[8];
    const float* w2  = (const float*)d_in[9];
    const float* b2  = (const float*)d_in[10];
    const float* wfc = (const float*)d_in[11];
    const float* bfc = (const float*)d_in[12];
    float* out = (float*)d_out;

    int V = in_sizes[0];
    if (V > V_MAX) V = V_MAX;

    int t32   = V * 32;
    int nblk  = (t32 + 255) / 256;

    k_pre<<<97, 512>>>(w2, wfc, b2, bfc);
    k_h  <<<nblk, 256>>>(vp, nb1, wv1, bv1, V);
    k_f1 <<<nblk, 256>>>(w1, b1, V);
    k_h2 <<<nblk, 256>>>(nb2, wv2, bv2, V);
    k_out<<<(V + 31) / 32, 256>>>(out, V);
}

// round 6
// speedup vs baseline: 1.8775x; 1.8775x over previous
#include <cuda_runtime.h>
#include <math_constants.h>

// ---------------------------------------------------------------------------
// CNNTest: graph conv (1->32) -> graph conv (32->64) -> FC(64->512) -> softmax
// V = 100000, N = 32 neighbors.
//
// R5 (resubmitted R6 after infra timeout): k_out = FFMA2 (fma.rn.f32x2) +
// COALESCED float4 B loads (lane ln owns cols {128j + 4*ln .. +3}, j=0..3 ->
// each LDG.128 is warp-contiguous 512B) + 64 vertices/CTA, 8 rows/warp
// (halves B wavefronts per FLOP). 1 CTA/SM.
// ---------------------------------------------------------------------------

#define V_MAX 100352
#define NNB   32

__device__ float g_h [V_MAX];
__device__ float g_f1[V_MAX * 32];
__device__ float g_h2[V_MAX * 32];
__device__ float g_Wc[96 * 512];
__device__ float g_bc[512];

// --------------------------- packed f32x2 helpers ---------------------------
__device__ __forceinline__ unsigned long long pack2(float x, float y) {
    unsigned long long r;
    asm("mov.b64 %0, {%1, %2};" : "=l"(r) : "f"(x), "f"(y));
    return r;
}
__device__ __forceinline__ void unpack2(unsigned long long p, float& x, float& y) {
    asm("mov.b64 {%0, %1}, %2;" : "=f"(x), "=f"(y) : "l"(p));
}
__device__ __forceinline__ unsigned long long ffma2(unsigned long long a,
                                                    unsigned long long b,
                                                    unsigned long long c) {
    unsigned long long d;
    asm("fma.rn.f32x2 %0, %1, %2, %3;" : "=l"(d) : "l"(a), "l"(b), "l"(c));
    return d;
}
__device__ __forceinline__ unsigned long long add2(unsigned long long a,
                                                   unsigned long long b) {
    unsigned long long d;
    asm("add.rn.f32x2 %0, %1, %2;" : "=l"(d) : "l"(a), "l"(b));
    return d;
}

// --------------------------- K1: first graph conv (to scalar h) ------------
__global__ void k_h(const float* __restrict__ vp, const int* __restrict__ nb1,
                    const float* __restrict__ wv1, const float* __restrict__ bv1,
                    int V) {
    int t = blockIdx.x * blockDim.x + threadIdx.x;
    int v = t >> 5;
    int j = t & 31;
    if (v >= V) return;
    float w0 = wv1[0], w1c = wv1[1], w2c = wv1[2], b = bv1[0];

    int   idx = nb1[v * NNB + j];
    float g   = vp[idx];
    float gm  = __shfl_up_sync(0xffffffffu, g, 1);
    float gp  = __shfl_down_sync(0xffffffffu, g, 1);
    if (j == 0)  gm = 0.f;
    if (j == 31) gp = 0.f;
    float c = fmaf(w0, gm, fmaf(w1c, g, fmaf(w2c, gp, b)));
    float r = fmaxf(c, 0.f);
#pragma unroll
    for (int s = 16; s > 0; s >>= 1)
        r += __shfl_xor_sync(0xffffffffu, r, s);
    if (j == 0) g_h[v] = r * (1.f / 32.f);
}

// --------------------------- K2: vertex conv 1 -> 32 channels --------------
__global__ void k_f1(const float* __restrict__ w1, const float* __restrict__ b1,
                     int V) {
    int t = blockIdx.x * blockDim.x + threadIdx.x;
    if (t >= V * 32) return;
    int v = t >> 5;
    int o = t & 31;
    float hm = (v > 0)     ? g_h[v - 1] : 0.f;
    float h0 = g_h[v];
    float hp = (v < V - 1) ? g_h[v + 1] : 0.f;
    g_f1[t] = fmaf(hm, w1[o * 3 + 0],
              fmaf(h0, w1[o * 3 + 1],
              fmaf(hp, w1[o * 3 + 2], b1[o])));
}

// --------------------------- K3: second graph conv (neighbor axis) ---------
__global__ void k_h2(const int* __restrict__ nb2,
                     const float* __restrict__ wv2, const float* __restrict__ bv2,
                     int V) {
    int t = blockIdx.x * blockDim.x + threadIdx.x;
    int v = t >> 5;
    int c = t & 31;
    if (v >= V) return;
    float w0 = wv2[0], w1c = wv2[1], w2c = wv2[2], b = bv2[0];

    int myidx = nb2[v * NNB + c];
    float g[32];
#pragma unroll
    for (int j = 0; j < 32; j++) {
        int ij = __shfl_sync(0xffffffffu, myidx, j);
        g[j] = g_f1[ij * 32 + c];
    }
    float acc = 0.f;
#pragma unroll
    for (int j = 0; j < 32; j++) {
        float gm = (j > 0)  ? g[j - 1] : 0.f;
        float gp = (j < 31) ? g[j + 1] : 0.f;
        acc += fmaxf(fmaf(w0, gm, fmaf(w1c, g[j], fmaf(w2c, gp, b))), 0.f);
    }
    g_h2[v * 32 + c] = acc * (1.f / 32.f);
}

// --------------------------- Kpre: fold w2 into wfc ------------------------
__global__ void k_pre(const float* __restrict__ w2, const float* __restrict__ wfc,
                      const float* __restrict__ b2, const float* __restrict__ bfc) {
    int p = threadIdx.x;       // 0..511
    int blk = blockIdx.x;      // 0..96
    if (blk < 96) {
        int k3 = blk >> 5;
        int c  = blk & 31;
        float s = 0.f;
#pragma unroll
        for (int o = 0; o < 64; o++)
            s = fmaf(w2[o * 96 + c * 3 + k3], wfc[p * 64 + o], s);
        g_Wc[blk * 512 + p] = s;
    } else {
        float s = bfc[p];
#pragma unroll
        for (int o = 0; o < 64; o++)
            s = fmaf(b2[o], wfc[p * 64 + o], s);
        g_bc[p] = s;
    }
}

// --------------------------- K4: fused GEMM + bias + softmax (FFMA2) -------
// Block: 256 threads = 8 warps, 64 vertices. Warp w: rows w*8..w*8+7.
// Lane ln: cols {128*j + 4*ln .. +3}, j=0..3 (16 cols) as 8 f32x2 pairs.
// B loads: float4, warp-contiguous 512B per instruction (4 wavefronts).
__global__ void __launch_bounds__(256, 1)
k_out(float* __restrict__ out, int V) {
    __shared__ float As[96 * 68];   // stride 68 floats (272B, 16B-aligned)
    int tid = threadIdx.x;
    int wp  = tid >> 5;
    int ln  = tid & 31;
    int v0  = blockIdx.x * 64;

    // Build A panel: As[K*68 + v] = h2[v0+v-1+k3][c], K = k3*32 + c, v=0..63
    for (int i = tid; i < 96 * 64; i += 256) {
        int K  = i % 96;
        int v  = i / 96;
        int k3 = K >> 5;
        int ch = K & 31;
        int row = v0 + v - 1 + k3;
        float val = (row >= 0 && row < V) ? g_h2[row * 32 + ch] : 0.f;
        As[K * 68 + v] = val;
    }
    __syncthreads();

    unsigned long long acc[8][8];
#pragma unroll
    for (int i = 0; i < 8; i++)
#pragma unroll
        for (int j = 0; j < 8; j++) acc[i][j] = 0ULL;   // (0.f, 0.f)

    const float4* __restrict__ Bp =
        (const float4*)(g_Wc) + ln;     // float4 index: k*128 + 32*j + ln

#pragma unroll 2
    for (int k = 0; k < 96; k++) {
        // A: 8 broadcast rows for this warp
        float4 alo = *(const float4*)&As[k * 68 + wp * 8];
        float4 ahi = *(const float4*)&As[k * 68 + wp * 8 + 4];
        unsigned long long ap[8];
        ap[0] = pack2(alo.x, alo.x); ap[1] = pack2(alo.y, alo.y);
        ap[2] = pack2(alo.z, alo.z); ap[3] = pack2(alo.w, alo.w);
        ap[4] = pack2(ahi.x, ahi.x); ap[5] = pack2(ahi.y, ahi.y);
        ap[6] = pack2(ahi.z, ahi.z); ap[7] = pack2(ahi.w, ahi.w);

        // B: 4 coalesced float4 loads -> 8 f32x2 pairs
        unsigned long long b[8];
#pragma unroll
        for (int j = 0; j < 4; j++) {
            float4 bv = __ldg(Bp + k * 128 + j * 32);
            b[2 * j]     = pack2(bv.x, bv.y);
            b[2 * j + 1] = pack2(bv.z, bv.w);
        }
#pragma unroll
        for (int i = 0; i < 8; i++)
#pragma unroll
            for (int j = 0; j < 8; j++)
                acc[i][j] = ffma2(ap[i], b[j], acc[i][j]);
    }

    // bias (packed, same column mapping)
    unsigned long long bb[8];
#pragma unroll
    for (int j = 0; j < 4; j++) {
        float4 bv = __ldg((const float4*)(g_bc) + j * 32 + ln);
        bb[2 * j]     = pack2(bv.x, bv.y);
        bb[2 * j + 1] = pack2(bv.z, bv.w);
    }

    // per-row softmax: row spans exactly one warp (16 cols/lane)
#pragma unroll
    for (int i = 0; i < 8; i++) {
        int v = v0 + wp * 8 + i;
        float vals[16];
        float m = -CUDART_INF_F;
#pragma unroll
        for (int j = 0; j < 8; j++) {
            unsigned long long s = add2(acc[i][j], bb[j]);
            unpack2(s, vals[2 * j], vals[2 * j + 1]);
            m = fmaxf(m, fmaxf(vals[2 * j], vals[2 * j + 1]));
        }
#pragma unroll
        for (int s = 16; s > 0; s >>= 1)
            m = fmaxf(m, __shfl_xor_sync(0xffffffffu, m, s));
        float sum = 0.f;
#pragma unroll
        for (int j = 0; j < 16; j++) {
            vals[j] = __expf(vals[j] - m);
            sum += vals[j];
        }
#pragma unroll
        for (int s = 16; s > 0; s >>= 1)
            sum += __shfl_xor_sync(0xffffffffu, sum, s);
        float inv = __fdividef(1.f, sum);
        if (v < V) {
            float* orow = out + (size_t)v * 512;
#pragma unroll
            for (int j = 0; j < 4; j++) {
                float4 o;
                o.x = vals[4 * j + 0] * inv;
                o.y = vals[4 * j + 1] * inv;
                o.z = vals[4 * j + 2] * inv;
                o.w = vals[4 * j + 3] * inv;
                *(float4*)(orow + j * 128 + 4 * ln) = o;
            }
        }
    }
}

// ---------------------------------------------------------------------------
extern "C" void kernel_launch(void* const* d_in, const int* in_sizes, int n_in,
                              void* d_out, int out_size) {
    const float* vp  = (const float*)d_in[0];
    const int*   nb1 = (const int*)  d_in[1];
    const int*   nb2 = (const int*)  d_in[2];
    const float* wv1 = (const float*)d_in[3];
    const float* bv1 = (const float*)d_in[4];
    const float* w1  = (const float*)d_in[5];
    const float* b1  = (const float*)d_in[6];
    const float* wv2 = (const float*)d_in[7];
    const float* bv2 = (const float*)d_in[8];
    const float* w2  = (const float*)d_in[9];
    const float* b2  = (const float*)d_in[10];
    const float* wfc = (const float*)d_in[11];
    const float* bfc = (const float*)d_in[12];
    float* out = (float*)d_out;

    int V = in_sizes[0];
    if (V > V_MAX) V = V_MAX;

    int t32   = V * 32;
    int nblk  = (t32 + 255) / 256;

    k_pre<<<97, 512>>>(w2, wfc, b2, bfc);
    k_h  <<<nblk, 256>>>(vp, nb1, wv1, bv1, V);
    k_f1 <<<nblk, 256>>>(w1, b1, V);
    k_h2 <<<nblk, 256>>>(nb2, wv2, bv2, V);
    k_out<<<(V + 63) / 64, 256>>>(out, V);
}

// round 11
// speedup vs baseline: 3.5173x; 1.8734x over previous
#include <cuda_runtime.h>
#include <cuda_bf16.h>
#include <math_constants.h>

// ---------------------------------------------------------------------------
// CNNTest: graph conv (1->32) -> graph conv (32->64) -> FC(64->512) -> softmax
// V = 100000, N = 32 neighbors.
//
// R7 (resubmitted R11; four infra failures): k_out on bf16 tensor cores
// (mma.sync.m16n8k16.f32.bf16).
//   - Wcomb folded (conv2 into FC) as before, now packed bf16 fragment-major
//     so each B-fragment load is one coalesced 128B LDG (L1-resident 98KB).
//   - CTA = 64 vertices x 512 cols, 8 warps x 64 cols; fp32 accumulators in
//     registers; cross-warp softmax via smem max/sum partials.
// fp32 fma roofline (~38TF/s) previously bound k_out at ~290us; tensor pipe
// removes that wall entirely.
// ---------------------------------------------------------------------------

#define V_MAX 100352
#define NNB   32

__device__ float g_h [V_MAX];
__device__ float g_f1[V_MAX * 32];
__device__ float g_h2[V_MAX * 32];
__device__ unsigned g_Wcb2[6 * 64 * 2 * 32];   // [kstep][ntile][b0/b1][lane] bf16x2
__device__ float g_bc[512];

// --------------------------- K1: first graph conv (to scalar h) ------------
__global__ void k_h(const float* __restrict__ vp, const int* __restrict__ nb1,
                    const float* __restrict__ wv1, const float* __restrict__ bv1,
                    int V) {
    int t = blockIdx.x * blockDim.x + threadIdx.x;
    int v = t >> 5;
    int j = t & 31;
    if (v >= V) return;
    float w0 = wv1[0], w1c = wv1[1], w2c = wv1[2], b = bv1[0];

    int   idx = nb1[v * NNB + j];
    float g   = vp[idx];
    float gm  = __shfl_up_sync(0xffffffffu, g, 1);
    float gp  = __shfl_down_sync(0xffffffffu, g, 1);
    if (j == 0)  gm = 0.f;
    if (j == 31) gp = 0.f;
    float c = fmaf(w0, gm, fmaf(w1c, g, fmaf(w2c, gp, b)));
    float r = fmaxf(c, 0.f);
#pragma unroll
    for (int s = 16; s > 0; s >>= 1)
        r += __shfl_xor_sync(0xffffffffu, r, s);
    if (j == 0) g_h[v] = r * (1.f / 32.f);
}

// --------------------------- K2: vertex conv 1 -> 32 channels --------------
__global__ void k_f1(const float* __restrict__ w1, const float* __restrict__ b1,
                     int V) {
    int t = blockIdx.x * blockDim.x + threadIdx.x;
    if (t >= V * 32) return;
    int v = t >> 5;
    int o = t & 31;
    float hm = (v > 0)     ? g_h[v - 1] : 0.f;
    float h0 = g_h[v];
    float hp = (v < V - 1) ? g_h[v + 1] : 0.f;
    g_f1[t] = fmaf(hm, w1[o * 3 + 0],
              fmaf(h0, w1[o * 3 + 1],
              fmaf(hp, w1[o * 3 + 2], b1[o])));
}

// --------------------------- K3: second graph conv (neighbor axis) ---------
__global__ void k_h2(const int* __restrict__ nb2,
                     const float* __restrict__ wv2, const float* __restrict__ bv2,
                     int V) {
    int t = blockIdx.x * blockDim.x + threadIdx.x;
    int v = t >> 5;
    int c = t & 31;
    if (v >= V) return;
    float w0 = wv2[0], w1c = wv2[1], w2c = wv2[2], b = bv2[0];

    int myidx = nb2[v * NNB + c];
    float g[32];
#pragma unroll
    for (int j = 0; j < 32; j++) {
        int ij = __shfl_sync(0xffffffffu, myidx, j);
        g[j] = g_f1[ij * 32 + c];
    }
    float acc = 0.f;
#pragma unroll
    for (int j = 0; j < 32; j++) {
        float gm = (j > 0)  ? g[j - 1] : 0.f;
        float gp = (j < 31) ? g[j + 1] : 0.f;
        acc += fmaxf(fmaf(w0, gm, fmaf(w1c, g[j], fmaf(w2c, gp, b))), 0.f);
    }
    g_h2[v * 32 + c] = acc * (1.f / 32.f);
}

// --------------------------- Kpack: fold w2 into wfc, pack bf16 frags ------
// Wcomb[K=k3*32+ch][n] = sum_o w2[o,ch,k3]*wfc[n,o]; stored as mma B fragments:
// word(idx) for idx = s*4096 + g*64 + h*32 + l:
//   k2 = 8s+4h+(l&3), n = 8g+(l>>2); word = bf16(Wc[2k2][n]) | bf16(Wc[2k2+1][n])<<16
__global__ void k_pack(const float* __restrict__ w2, const float* __restrict__ wfc,
                       const float* __restrict__ b2, const float* __restrict__ bfc) {
    int blk = blockIdx.x;
    int tid = threadIdx.x;
    if (blk < 48) {
        int idx = blk * 512 + tid;
        int l = idx & 31;
        int h = (idx >> 5) & 1;
        int g = (idx >> 6) & 63;
        int s = idx >> 12;
        int k2 = 8 * s + 4 * h + (l & 3);
        int n  = 8 * g + (l >> 2);
        float v[2];
#pragma unroll
        for (int q = 0; q < 2; q++) {
            int K  = 2 * k2 + q;
            int k3 = K >> 5;
            int ch = K & 31;
            float sacc = 0.f;
#pragma unroll
            for (int o = 0; o < 64; o++)
                sacc = fmaf(w2[o * 96 + ch * 3 + k3], wfc[n * 64 + o], sacc);
            v[q] = sacc;
        }
        __nv_bfloat162 t = __floats2bfloat162_rn(v[0], v[1]);
        g_Wcb2[idx] = *(unsigned*)&t;
    } else {
        int p = tid;
        float s = bfc[p];
#pragma unroll
        for (int o = 0; o < 64; o++)
            s = fmaf(b2[o], wfc[p * 64 + o], s);
        g_bc[p] = s;
    }
}

// --------------------------- K4: tensor-core GEMM + bias + softmax ---------
// CTA: 256 threads = 8 warps, 64 vertices x 512 cols. Warp w owns cols
// [w*64, w*64+64). A panel [64 x 96] bf16 in smem (stride 104 -> conflict-free
// frag LDS). mma.sync.m16n8k16 row.col f32.bf16: 4 m-tiles x 8 n-tiles x 6 k.
__global__ void __launch_bounds__(256, 1)
k_out(float* __restrict__ out, int V) {
    __shared__ unsigned short As[64 * 104];
    __shared__ float redm[64][9];
    __shared__ float reds[64][9];
    int tid = threadIdx.x;
    int wp  = tid >> 5;
    int l   = tid & 31;
    int v0  = blockIdx.x * 64;

    // Build A panel (bf16): As[v*104 + K] = h2[v0+v-1+k3][ch], K=k3*32+ch
    for (int i = tid; i < 64 * 96; i += 256) {
        int v  = i / 96;
        int K  = i % 96;
        int k3 = K >> 5;
        int ch = K & 31;
        int row = v0 + v - 1 + k3;
        float val = (row >= 0 && row < V) ? g_h2[row * 32 + ch] : 0.f;
        As[v * 104 + K] = __bfloat16_as_ushort(__float2bfloat16(val));
    }
    __syncthreads();

    float acc[4][8][4];
#pragma unroll
    for (int m = 0; m < 4; m++)
#pragma unroll
        for (int nt = 0; nt < 8; nt++)
#pragma unroll
            for (int q = 0; q < 4; q++) acc[m][nt][q] = 0.f;

    int lq = l >> 2;        // 0..7
    int lr = l & 3;         // 0..3

#pragma unroll
    for (int s = 0; s < 6; s++) {
        // A fragments: 4 m-tiles x 4 regs
        unsigned a[4][4];
#pragma unroll
        for (int m = 0; m < 4; m++) {
            int r0 = (m * 16 + lq) * 104 + s * 16 + lr * 2;
            a[m][0] = *(const unsigned*)&As[r0];
            a[m][1] = *(const unsigned*)&As[r0 + 8 * 104];
            a[m][2] = *(const unsigned*)&As[r0 + 8];
            a[m][3] = *(const unsigned*)&As[r0 + 8 * 104 + 8];
        }
#pragma unroll
        for (int nt = 0; nt < 8; nt++) {
            int gg = wp * 8 + nt;
            unsigned b0 = g_Wcb2[((s * 64 + gg) * 2 + 0) * 32 + l];
            unsigned b1 = g_Wcb2[((s * 64 + gg) * 2 + 1) * 32 + l];
#pragma unroll
            for (int m = 0; m < 4; m++) {
                asm volatile(
                    "mma.sync.aligned.m16n8k16.row.col.f32.bf16.bf16.f32 "
                    "{%0,%1,%2,%3}, {%4,%5,%6,%7}, {%8,%9}, {%0,%1,%2,%3};"
                    : "+f"(acc[m][nt][0]), "+f"(acc[m][nt][1]),
                      "+f"(acc[m][nt][2]), "+f"(acc[m][nt][3])
                    : "r"(a[m][0]), "r"(a[m][1]), "r"(a[m][2]), "r"(a[m][3]),
                      "r"(b0), "r"(b1));
            }
        }
    }

    // bias: cols w*64 + nt*8 + lr*2 (+1); rows (c0,c1)=lq, (c2,c3)=lq+8
    float2 bb[8];
#pragma unroll
    for (int nt = 0; nt < 8; nt++)
        bb[nt] = *(const float2*)&g_bc[wp * 64 + nt * 8 + lr * 2];
#pragma unroll
    for (int m = 0; m < 4; m++)
#pragma unroll
        for (int nt = 0; nt < 8; nt++) {
            acc[m][nt][0] += bb[nt].x;
            acc[m][nt][1] += bb[nt].y;
            acc[m][nt][2] += bb[nt].x;
            acc[m][nt][3] += bb[nt].y;
        }

    // ---- softmax phase 1: per-warp row max -> smem ----
#pragma unroll
    for (int m = 0; m < 4; m++)
#pragma unroll
        for (int hf = 0; hf < 2; hf++) {
            float lm = -CUDART_INF_F;
#pragma unroll
            for (int nt = 0; nt < 8; nt++)
                lm = fmaxf(lm, fmaxf(acc[m][nt][hf * 2], acc[m][nt][hf * 2 + 1]));
            lm = fmaxf(lm, __shfl_xor_sync(0xffffffffu, lm, 1));
            lm = fmaxf(lm, __shfl_xor_sync(0xffffffffu, lm, 2));
            int r = m * 16 + hf * 8 + lq;
            if (lr == 0) redm[r][wp] = lm;
        }
    __syncthreads();

    // ---- phase 2: global max, exp, per-warp sum -> smem ----
#pragma unroll
    for (int m = 0; m < 4; m++)
#pragma unroll
        for (int hf = 0; hf < 2; hf++) {
            int r = m * 16 + hf * 8 + lq;
            float mm = redm[r][0];
#pragma unroll
            for (int j = 1; j < 8; j++) mm = fmaxf(mm, redm[r][j]);
            float ls = 0.f;
#pragma unroll
            for (int nt = 0; nt < 8; nt++) {
                float e0 = __expf(acc[m][nt][hf * 2]     - mm);
                float e1 = __expf(acc[m][nt][hf * 2 + 1] - mm);
                acc[m][nt][hf * 2]     = e0;
                acc[m][nt][hf * 2 + 1] = e1;
                ls += e0 + e1;
            }
            ls += __shfl_xor_sync(0xffffffffu, ls, 1);
            ls += __shfl_xor_sync(0xffffffffu, ls, 2);
            if (lr == 0) reds[r][wp] = ls;
        }
    __syncthreads();

    // ---- phase 3: normalize + store ----
#pragma unroll
    for (int m = 0; m < 4; m++)
#pragma unroll
        for (int hf = 0; hf < 2; hf++) {
            int r = m * 16 + hf * 8 + lq;
            float S = reds[r][0];
#pragma unroll
            for (int j = 1; j < 8; j++) S += reds[r][j];
            float inv = __fdividef(1.f, S);
            int v = v0 + r;
            if (v < V) {
                float* orow = out + (size_t)v * 512 + wp * 64 + lr * 2;
#pragma unroll
                for (int nt = 0; nt < 8; nt++) {
                    float2 o;
                    o.x = acc[m][nt][hf * 2]     * inv;
                    o.y = acc[m][nt][hf * 2 + 1] * inv;
                    *(float2*)(orow + nt * 8) = o;
                }
            }
        }
}

// ---------------------------------------------------------------------------
extern "C" void kernel_launch(void* const* d_in, const int* in_sizes, int n_in,
                              void* d_out, int out_size) {
    const float* vp  = (const float*)d_in[0];
    const int*   nb1 = (const int*)  d_in[1];
    const int*   nb2 = (const int*)  d_in[2];
    const float* wv1 = (const float*)d_in[3];
    const float* bv1 = (const float*)d_in[4];
    const float* w1  = (const float*)d_in[5];
    const float* b1  = (const float*)d_in[6];
    const float* wv2 = (const float*)d_in[7];
    const float* bv2 = (const float*)d_in[8];
    const float* w2  = (const float*)d_in[9];
    const float* b2  = (const float*)d_in[10];
    const float* wfc = (const float*)d_in[11];
    const float* bfc = (const float*)d_in[12];
    float* out = (float*)d_out;

    int V = in_sizes[0];
    if (V > V_MAX) V = V_MAX;

    int t32   = V * 32;
    int nblk  = (t32 + 255) / 256;

    k_pack<<<49, 512>>>(w2, wfc, b2, bfc);
    k_h  <<<nblk, 256>>>(vp, nb1, wv1, bv1, V);
    k_f1 <<<nblk, 256>>>(w1, b1, V);
    k_h2 <<<nblk, 256>>>(nb2, wv2, bv2, V);
    k_out<<<(V + 63) / 64, 256>>>(out, V);
}